// round 10
// baseline (speedup 1.0000x reference)
#include <cuda_runtime.h>
#include <cuda_fp16.h>

#define NROWS 32768
#define DDIM  64
#define KCB   1024
#define MT    128
#define NLOC  512                  // codes per CTA (half codebook)
#define TLOC  4                    // 128-col tiles per CTA
#define NTHREADS 256

#define O_ZQ    0
#define O_LOSS  2097152
#define O_PERP  2097153
#define O_IDX   2097154
#define O_DIST  2129922

// K layout: 64 halves + pad -> pitch 72 (fragment lanes (lg,q) hit banks 4lg+q: conflict-free)
#define KP 72

// main smem offsets (bytes)
#define S_A    0                   // 128 x 144 = 18432
#define S_B    18432               // 512 x 144 = 73728
#define S_E2   92160               // 512 f32
#define S_F2   94208               // 128 f32
#define SMEM_BYTES 94720           // x2 = 189440 <= 227KB -> 2 CTAs/SM

#define ESCALE 1024.0f
#define DSCALE (-2.0f / 1024.0f)   // exact power of two
#define MARGIN 6e-4f

__device__ float         g_loss;
__device__ unsigned int  g_counts[KCB];
__device__ float         g_e2[KCB];
__device__ float         g_f2[NROWS];
__device__ float2        g_cand[512 * 128 * 16];   // [cta][row][slot] = 8 MB

__device__ __forceinline__ void mma16816(float* c, const unsigned* a,
                                         unsigned b0, unsigned b1) {
    asm volatile(
        "mma.sync.aligned.m16n8k16.row.col.f32.f16.f16.f32 "
        "{%0,%1,%2,%3}, {%4,%5,%6,%7}, {%8,%9}, {%0,%1,%2,%3};"
        : "+f"(c[0]), "+f"(c[1]), "+f"(c[2]), "+f"(c[3])
        : "r"(a[0]), "r"(a[1]), "r"(a[2]), "r"(a[3]), "r"(b0), "r"(b1));
}

// ---- main: convert + GEMM + approx dists + per-row candidate slots ----
__global__ void __launch_bounds__(NTHREADS, 2)
vq_main_kernel(const float* __restrict__ z_e,
               const float* __restrict__ emb,
               float* __restrict__ dist_out)
{
    extern __shared__ unsigned char smem[];
    const int t = threadIdx.x, lane = t & 31, w = t >> 5;
    const int wm = w & 3, wn = w >> 2;
    const int q = lane & 3, lg = lane >> 2;

    const int rb = blockIdx.x >> 1, h = blockIdx.x & 1;
    const int n0 = rb * MT, b = n0 >> 10, hw0 = n0 & 1023;
    const float* zbase = z_e + (size_t)b * (DDIM * 1024) + hw0;

    __half* A_s  = (__half*)(smem + S_A);
    __half* B_s  = (__half*)(smem + S_B);
    float*  e2_s = (float*)(smem + S_E2);
    float*  f2_s = (float*)(smem + S_F2);

    if (blockIdx.x == 0) {          // zero scratch; combine runs after kernel boundary
        for (int i = t; i < KCB; i += NTHREADS) g_counts[i] = 0u;
        if (t == 0) g_loss = 0.0f;
    }

    // B convert: 2 codes/thread; e2 with R9-prepack arithmetic (4-sums + binary fold)
    #pragma unroll 1
    for (int cc = 0; cc < 2; ++cc) {
        const int cl = cc * NTHREADS + t;           // local code 0..511
        const int k  = h * NLOC + cl;
        const float* ep = emb + (size_t)k * DDIM;
        __half* row = B_s + cl * KP;
        float v[16];
        #pragma unroll
        for (int p = 0; p < 16; ++p) {
            float4 x = *(const float4*)(ep + p * 4);
            float e2p = 0.0f;
            e2p = fmaf(x.x, x.x, e2p);
            e2p = fmaf(x.y, x.y, e2p);
            e2p = fmaf(x.z, x.z, e2p);
            e2p = fmaf(x.w, x.w, e2p);
            v[p] = e2p;
            *(__half2*)(row + p * 4) =
                __halves2half2(__float2half_rn(x.x * ESCALE), __float2half_rn(x.y * ESCALE));
            *(__half2*)(row + p * 4 + 2) =
                __halves2half2(__float2half_rn(x.z * ESCALE), __float2half_rn(x.w * ESCALE));
        }
        #pragma unroll
        for (int o = 8; o > 0; o >>= 1)
            #pragma unroll
            for (int p = 0; p < 8; ++p)
                if (p < o) v[p] = v[p] + v[p + o];
        e2_s[cl] = v[0];
        if (rb == 0) g_e2[k] = v[0];
    }

    // A build + f2 (R9 verbatim arithmetic)
    {
        const int m = t >> 1, hf = t & 1;
        __half* arow = A_s + m * KP;
        float f2p = 0.0f;
        #pragma unroll
        for (int i = 0; i < 32; i += 2) {
            int d = hf * 32 + i;
            float x0 = zbase[(size_t)d * 1024 + m];
            float x1 = zbase[(size_t)(d + 1) * 1024 + m];
            f2p = fmaf(x0, x0, f2p);
            f2p = fmaf(x1, x1, f2p);
            *(__half2*)(arow + d) =
                __halves2half2(__float2half_rn(x0), __float2half_rn(x1));
        }
        float oth = __shfl_xor_sync(0xffffffffu, f2p, 1);
        if (hf == 0) {
            f2_s[m] = f2p + oth;
            if (h == 0) g_f2[n0 + m] = f2p + oth;
        }
    }
    __syncthreads();

    float v1[4], v2[4];
    int   i1[4], i2[4];
    #pragma unroll
    for (int i = 0; i < 4; ++i) { v1[i] = 3.0e38f; v2[i] = 3.0e38f; i1[i] = 0; i2[i] = 0; }

    const float f2a0 = f2_s[wm * 32 + lg];
    const float f2b0 = f2_s[wm * 32 + lg + 8];
    const float f2a1 = f2_s[wm * 32 + 16 + lg];
    const float f2b1 = f2_s[wm * 32 + 16 + lg + 8];

    #pragma unroll 1
    for (int t8 = 0; t8 < TLOC; ++t8) {
        const __half* Bt = B_s + t8 * 128 * KP;

        float C[2][8][4];
        #pragma unroll
        for (int mt = 0; mt < 2; ++mt)
            #pragma unroll
            for (int nt = 0; nt < 8; ++nt)
                #pragma unroll
                for (int r = 0; r < 4; ++r) C[mt][nt][r] = 0.0f;

        #pragma unroll
        for (int kt = 0; kt < 4; ++kt) {
            const int k0 = kt * 16 + 2 * q;
            unsigned a[2][4];
            #pragma unroll
            for (int mt = 0; mt < 2; ++mt) {
                const int r = wm * 32 + mt * 16 + lg;
                a[mt][0] = *(const unsigned*)(A_s + r * KP + k0);
                a[mt][1] = *(const unsigned*)(A_s + (r + 8) * KP + k0);
                a[mt][2] = *(const unsigned*)(A_s + r * KP + k0 + 8);
                a[mt][3] = *(const unsigned*)(A_s + (r + 8) * KP + k0 + 8);
            }
            #pragma unroll
            for (int nt = 0; nt < 8; ++nt) {
                const int n = wn * 64 + nt * 8 + lg;
                unsigned b0 = *(const unsigned*)(Bt + n * KP + k0);
                unsigned b1 = *(const unsigned*)(Bt + n * KP + k0 + 8);
                mma16816(C[0][nt], a[0], b0, b1);
                mma16816(C[1][nt], a[1], b0, b1);
            }
        }

        #pragma unroll
        for (int mt = 0; mt < 2; ++mt) {
            const int r = wm * 32 + mt * 16 + lg;
            const float f2a = mt ? f2a1 : f2a0;
            const float f2b = mt ? f2b1 : f2b0;
            const int ra = mt * 2, rbi = mt * 2 + 1;
            float* dra = dist_out + (size_t)(n0 + r) * KCB;
            float* drb = dist_out + (size_t)(n0 + r + 8) * KCB;
            #pragma unroll
            for (int nt = 0; nt < 8; ++nt) {
                const int cl  = t8 * 128 + wn * 64 + nt * 8 + 2 * q;   // local col
                const int col = h * NLOC + cl;                          // global col
                const float e2x = e2_s[cl], e2y = e2_s[cl + 1];
                float d0 = fmaf(DSCALE, C[mt][nt][0], f2a + e2x);
                float d1 = fmaf(DSCALE, C[mt][nt][1], f2a + e2y);
                float d2 = fmaf(DSCALE, C[mt][nt][2], f2b + e2x);
                float d3 = fmaf(DSCALE, C[mt][nt][3], f2b + e2y);
                if (d0 < v1[ra]) { v2[ra]=v1[ra]; i2[ra]=i1[ra]; v1[ra]=d0; i1[ra]=col; }
                else if (d0 < v2[ra]) { v2[ra]=d0; i2[ra]=col; }
                if (d1 < v1[ra]) { v2[ra]=v1[ra]; i2[ra]=i1[ra]; v1[ra]=d1; i1[ra]=col+1; }
                else if (d1 < v2[ra]) { v2[ra]=d1; i2[ra]=col+1; }
                if (d2 < v1[rbi]) { v2[rbi]=v1[rbi]; i2[rbi]=i1[rbi]; v1[rbi]=d2; i1[rbi]=col; }
                else if (d2 < v2[rbi]) { v2[rbi]=d2; i2[rbi]=col; }
                if (d3 < v1[rbi]) { v2[rbi]=v1[rbi]; i2[rbi]=i1[rbi]; v1[rbi]=d3; i1[rbi]=col+1; }
                else if (d3 < v2[rbi]) { v2[rbi]=d3; i2[rbi]=col+1; }
                *(float2*)(dra + col) = make_float2(d0, d1);
                *(float2*)(drb + col) = make_float2(d2, d3);
            }
        }
    }

    // dump 16 slots per row for this half
    float2* cb = g_cand + (size_t)blockIdx.x * (128 * 16);
    #pragma unroll
    for (int ri = 0; ri < 4; ++ri) {
        const int row = wm * 32 + (ri >> 1) * 16 + (ri & 1) * 8 + lg;
        const int base = row * 16 + wn * 8 + q * 2;
        cb[base]     = make_float2(v1[ri], __int_as_float(i1[ri]));
        cb[base + 1] = make_float2(v2[ri], __int_as_float(i2[ri]));
    }
}

// ---- combine: merge 32 slots/row, margin refine, idx/hist/zq/loss ----
__global__ void __launch_bounds__(NTHREADS)
vq_combine_kernel(const float* __restrict__ z_e,
                  const float* __restrict__ emb,
                  float* __restrict__ zq_out,
                  float* __restrict__ idx_out)
{
    __shared__ int   idx_s[MT];
    __shared__ float red[NTHREADS];
    const int t = threadIdx.x, lane = t & 31, w = t >> 5;
    const int rb = blockIdx.x;
    const int n0 = rb * MT, b = n0 >> 10, hw0 = n0 & 1023;
    const float* zbase = z_e + (size_t)b * (DDIM * 1024) + hw0;

    const float2* c0 = g_cand + (size_t)(rb * 2)     * (128 * 16);
    const float2* c1 = g_cand + (size_t)(rb * 2 + 1) * (128 * 16);

    for (int j = 0; j < 16; ++j) {
        const int row = w * 16 + j;
        const float f2row = g_f2[n0 + row];
        float2 e = (lane < 16) ? c0[row * 16 + lane] : c1[row * 16 + (lane - 16)];
        float cv = e.x;
        int   ci = __float_as_int(e.y);
        float vmin = cv;
        #pragma unroll
        for (int off = 16; off > 0; off >>= 1)
            vmin = fminf(vmin, __shfl_xor_sync(0xffffffffu, vmin, off));
        unsigned mask = __ballot_sync(0xffffffffu, cv <= vmin + MARGIN);
        int widx;
        if (__popc(mask) == 1) {
            widx = __shfl_sync(0xffffffffu, ci, __ffs(mask) - 1);
        } else {
            const int d0 = 2 * lane, d1 = 2 * lane + 1;
            const float z0 = zbase[(size_t)d0 * 1024 + row];
            const float z1 = zbase[(size_t)d1 * 1024 + row];
            float bs = 3.0e38f;
            int   bidx = 0x7fffffff;
            unsigned mm = mask;
            while (mm) {
                const int src = __ffs(mm) - 1;
                mm &= mm - 1;
                const int cidx = __shfl_sync(0xffffffffu, ci, src);
                const float* er = emb + (size_t)cidx * DDIM;
                float p = fmaf(z0, er[d0], z1 * er[d1]);
                #pragma unroll
                for (int off = 16; off > 0; off >>= 1)
                    p += __shfl_xor_sync(0xffffffffu, p, off);
                float s = fmaf(-2.0f, p, f2row + g_e2[cidx]);  // reference tie grid
                if (s < bs || (s == bs && cidx < bidx)) { bs = s; bidx = cidx; }
            }
            widx = bidx;
        }
        if (lane == 0) {
            idx_s[row] = widx;
            idx_out[n0 + row] = (float)widx;
            atomicAdd(&g_counts[widx], 1u);
        }
    }
    __syncthreads();

    float lsum = 0.0f;
    {
        const int m = t >> 1, hf = t & 1;
        const int bi = idx_s[m];
        const float* erow = emb + (size_t)bi * DDIM;
        float* zq_base = zq_out + (size_t)b * (DDIM * 1024) + hw0;
        #pragma unroll
        for (int i = 0; i < 32; ++i) {
            int d = hf * 32 + i;
            float v  = erow[d];
            float fv = zbase[(size_t)d * 1024 + m];
            float df = v - fv;
            lsum = fmaf(df, df, lsum);
            zq_base[(size_t)d * 1024 + m] = v;
        }
    }
    red[t] = lsum;
    __syncthreads();
    #pragma unroll
    for (int s = 128; s > 0; s >>= 1) {
        if (t < s) red[t] += red[t + s];
        __syncthreads();
    }
    if (t == 0) atomicAdd(&g_loss, red[0]);
}

__global__ void vq_finalize_kernel(float* __restrict__ loss_out,
                                   float* __restrict__ perp_out)
{
    __shared__ float red[KCB];
    int t = threadIdx.x;
    float c = (float)g_counts[t];
    float p = c * (1.0f / (float)NROWS);
    red[t] = p * logf(p + 1e-10f);
    __syncthreads();
    #pragma unroll
    for (int s = KCB / 2; s > 0; s >>= 1) {
        if (t < s) red[t] += red[t + s];
        __syncthreads();
    }
    if (t == 0) {
        *perp_out = expf(-red[0]);
        *loss_out = g_loss * (1.25f / (float)(NROWS * DDIM));
    }
}

extern "C" void kernel_launch(void* const* d_in, const int* in_sizes, int n_in,
                              void* d_out, int out_size)
{
    const float* z_e = (const float*)d_in[0];
    const float* emb = (const float*)d_in[1];
    float* out = (float*)d_out;

    cudaFuncSetAttribute(vq_main_kernel,
                         cudaFuncAttributeMaxDynamicSharedMemorySize, SMEM_BYTES);

    vq_main_kernel<<<512, NTHREADS, SMEM_BYTES>>>(z_e, emb, out + O_DIST);
    vq_combine_kernel<<<NROWS / MT, NTHREADS>>>(z_e, emb, out + O_ZQ, out + O_IDX);
    vq_finalize_kernel<<<1, KCB>>>(out + O_LOSS, out + O_PERP);
}

// round 11
// speedup vs baseline: 1.2492x; 1.2492x over previous
#include <cuda_runtime.h>
#include <cuda_fp16.h>

#define NROWS 32768
#define DDIM  64
#define KCB   1024
#define MT    128
#define NTILES 8
#define NTHREADS 512

#define O_ZQ    0
#define O_LOSS  2097152
#define O_PERP  2097153
#define O_IDX   2097154
#define O_DIST  2129922

// K layout: 64 halves + pad -> pitch 72 (rows 16B-aligned, ldmatrix conflict-free)
#define KP 72
#define B_TILE 18432               // 128 codes x 144 B
#define B_ALL  147456              // full codebook resident

// smem byte offsets
#define S_A    0                   // 128 x 144 = 18432
#define S_B    18432               // 147456
#define S_E2   165888              // 1024 f32
#define S_F2   169984              // 128 f32
#define S_CAND 170496              // 128 rows x 32 slots x 8B = 32768
#define S_IDX  203264              // 128 i32
#define S_RED  203776              // 512 f32
#define SMEM_BYTES 205824

#define ESCALE 1024.0f
#define DSCALE (-2.0f / 1024.0f)   // exact power of two
#define MARGIN 6e-4f

__device__ float         g_loss;
__device__ unsigned int  g_counts[KCB];
__device__ float         g_e2[KCB];
__device__ __align__(16) unsigned char g_epack[B_ALL];

__device__ __forceinline__ unsigned smem_u32(const void* p) {
    unsigned a;
    asm("{ .reg .u64 t; cvta.to.shared.u64 t, %1; cvt.u32.u64 %0, t; }"
        : "=r"(a) : "l"(p));
    return a;
}
__device__ __forceinline__ void cp16(unsigned dst, const void* src) {
    asm volatile("cp.async.cg.shared.global [%0], [%1], 16;" :: "r"(dst), "l"(src));
}
#define CP_COMMIT() asm volatile("cp.async.commit_group;" ::: "memory")
#define CP_WAIT0()  asm volatile("cp.async.wait_group 0;"  ::: "memory")

#define LDSM4(r0, r1, r2, r3, addr) \
    asm volatile("ldmatrix.sync.aligned.m8n8.x4.shared.b16 {%0,%1,%2,%3}, [%4];" \
        : "=r"(r0), "=r"(r1), "=r"(r2), "=r"(r3) : "r"(addr))

__device__ __forceinline__ void mma16816(float* c, const unsigned* a,
                                         unsigned b0, unsigned b1) {
    asm volatile(
        "mma.sync.aligned.m16n8k16.row.col.f32.f16.f16.f32 "
        "{%0,%1,%2,%3}, {%4,%5,%6,%7}, {%8,%9}, {%0,%1,%2,%3};"
        : "+f"(c[0]), "+f"(c[1]), "+f"(c[2]), "+f"(c[3])
        : "r"(a[0]), "r"(a[1]), "r"(a[2]), "r"(a[3]), "r"(b0), "r"(b1));
}

// ---- prepack: g1 = fp16(1024*emb) rows (pitch KP) + e2; block 64 zeroes scratch ----
__global__ void vq_prepack_kernel(const float* __restrict__ emb) {
    const int t = threadIdx.x;
    if (blockIdx.x == 64) {
        for (int i = t; i < KCB; i += 256) g_counts[i] = 0u;
        if (t == 0) g_loss = 0.0f;
        return;
    }
    const int kk = t >> 4, part = t & 15;
    const int k = blockIdx.x * 16 + kk;
    const float* ep = emb + (size_t)k * DDIM + part * 4;
    __half* row = (__half*)(g_epack + (size_t)k * (KP * 2));
    float e2p = 0.0f;
    #pragma unroll
    for (int i = 0; i < 4; i += 2) {
        float x0 = ep[i], x1 = ep[i + 1];
        e2p = fmaf(x0, x0, e2p);
        e2p = fmaf(x1, x1, e2p);
        __half a0 = __float2half_rn(x0 * ESCALE);
        __half a1 = __float2half_rn(x1 * ESCALE);
        *(__half2*)(row + part * 4 + i) = __halves2half2(a0, a1);
    }
    #pragma unroll
    for (int off = 8; off > 0; off >>= 1)
        e2p += __shfl_xor_sync(0xffffffffu, e2p, off, 16);
    if (part == 0) g_e2[k] = e2p;
}

__global__ void __launch_bounds__(NTHREADS, 1)
vq_main_kernel(const float* __restrict__ z_e,
               const float* __restrict__ emb,
               float* __restrict__ zq_out,
               float* __restrict__ idx_out,
               float* __restrict__ dist_out)
{
    extern __shared__ unsigned char smem[];
    const unsigned sbase = smem_u32(smem);
    const int t = threadIdx.x, lane = t & 31, w = t >> 5;
    const int wm = w & 3, wn = w >> 2;      // 16 warps: 4 row-quads x 4 col-quarters
    const int q = lane & 3, lg = lane >> 2;

    const int n0 = blockIdx.x * MT, b = n0 >> 10, hw0 = n0 & 1023;
    const float* zbase = z_e + (size_t)b * (DDIM * 1024) + hw0;

    __half* A_s  = (__half*)(smem + S_A);
    float*  e2_s = (float*)(smem + S_E2);
    float*  f2_s = (float*)(smem + S_F2);
    float2* cand = (float2*)(smem + S_CAND);
    int*    idx_s = (int*)(smem + S_IDX);
    float*  red  = (float*)(smem + S_RED);

    // codebook -> smem (coalesced cp.async, 18 x 16B per thread)
    #pragma unroll
    for (int i = 0; i < 18; ++i) {
        int c = i * NTHREADS + t;
        cp16(sbase + S_B + c * 16, g_epack + c * 16);
    }
    CP_COMMIT();

    // A build + f2: m = t>>2, 16 d's per thread
    {
        const int m = t >> 2, part = t & 3;
        __half* arow = A_s + m * KP;
        float f2p = 0.0f;
        #pragma unroll
        for (int i = 0; i < 16; i += 2) {
            int d = part * 16 + i;
            float x0 = zbase[(size_t)d * 1024 + m];
            float x1 = zbase[(size_t)(d + 1) * 1024 + m];
            f2p = fmaf(x0, x0, f2p);
            f2p = fmaf(x1, x1, f2p);
            *(__half2*)(arow + d) =
                __halves2half2(__float2half_rn(x0), __float2half_rn(x1));
        }
        f2p += __shfl_xor_sync(0xffffffffu, f2p, 1, 4);
        f2p += __shfl_xor_sync(0xffffffffu, f2p, 2, 4);
        if (part == 0) f2_s[m] = f2p;
    }
    #pragma unroll
    for (int i = 0; i < 2; ++i) e2_s[i * NTHREADS + t] = g_e2[i * NTHREADS + t];
    CP_WAIT0();
    __syncthreads();

    // ldmatrix base addresses (verified identical lane mapping to mma frags)
    const unsigned a_addr0 = sbase + S_A +
        (unsigned)(((wm * 32 + (lane & 15)) * KP + 8 * (lane >> 4)) * 2);
    const unsigned a_addr1 = a_addr0 + 16 * KP * 2;
    const unsigned b_addr0 = sbase + S_B +
        (unsigned)(((wn * 32 + 8 * (lane >> 4) + (lane & 7)) * KP
                    + 8 * ((lane >> 3) & 1)) * 2);

    float v1[4], v2[4];
    int   i1[4], i2[4];
    #pragma unroll
    for (int i = 0; i < 4; ++i) { v1[i] = 3.0e38f; v2[i] = 3.0e38f; i1[i] = 0; i2[i] = 0; }

    const float f2a0 = f2_s[wm * 32 + lg];
    const float f2b0 = f2_s[wm * 32 + lg + 8];
    const float f2a1 = f2_s[wm * 32 + 16 + lg];
    const float f2b1 = f2_s[wm * 32 + 16 + lg + 8];

    #pragma unroll 1
    for (int t8 = 0; t8 < NTILES; ++t8) {
        const unsigned bt = b_addr0 + t8 * B_TILE;

        float C[2][4][4];
        #pragma unroll
        for (int mt = 0; mt < 2; ++mt)
            #pragma unroll
            for (int nt = 0; nt < 4; ++nt)
                #pragma unroll
                for (int r = 0; r < 4; ++r) C[mt][nt][r] = 0.0f;

        #pragma unroll
        for (int kt = 0; kt < 4; ++kt) {
            unsigned a0[4], a1[4], bb[8];
            LDSM4(a0[0], a0[1], a0[2], a0[3], a_addr0 + kt * 32);
            LDSM4(a1[0], a1[1], a1[2], a1[3], a_addr1 + kt * 32);
            LDSM4(bb[0], bb[1], bb[2], bb[3], bt + kt * 32);          // nt 0,1
            LDSM4(bb[4], bb[5], bb[6], bb[7], bt + 2304 + kt * 32);   // nt 2,3
            mma16816(C[0][0], a0, bb[0], bb[1]);
            mma16816(C[1][0], a1, bb[0], bb[1]);
            mma16816(C[0][1], a0, bb[2], bb[3]);
            mma16816(C[1][1], a1, bb[2], bb[3]);
            mma16816(C[0][2], a0, bb[4], bb[5]);
            mma16816(C[1][2], a1, bb[4], bb[5]);
            mma16816(C[0][3], a0, bb[6], bb[7]);
            mma16816(C[1][3], a1, bb[6], bb[7]);
        }

        // epilogue: approx distances, top-2 track, direct float2 stores
        #pragma unroll
        for (int mt = 0; mt < 2; ++mt) {
            const int r = wm * 32 + mt * 16 + lg;
            const float f2a = mt ? f2a1 : f2a0;
            const float f2b = mt ? f2b1 : f2b0;
            const int ra = mt * 2, rb = mt * 2 + 1;
            float* dra = dist_out + (size_t)(n0 + r) * KCB;
            float* drb = dist_out + (size_t)(n0 + r + 8) * KCB;
            #pragma unroll
            for (int nt = 0; nt < 4; ++nt) {
                const int col = t8 * 128 + wn * 32 + nt * 8 + 2 * q;
                const float e2x = e2_s[col], e2y = e2_s[col + 1];
                float d0 = fmaf(DSCALE, C[mt][nt][0], f2a + e2x);
                float d1 = fmaf(DSCALE, C[mt][nt][1], f2a + e2y);
                float d2 = fmaf(DSCALE, C[mt][nt][2], f2b + e2x);
                float d3 = fmaf(DSCALE, C[mt][nt][3], f2b + e2y);
                if (d0 < v1[ra]) { v2[ra]=v1[ra]; i2[ra]=i1[ra]; v1[ra]=d0; i1[ra]=col; }
                else if (d0 < v2[ra]) { v2[ra]=d0; i2[ra]=col; }
                if (d1 < v1[ra]) { v2[ra]=v1[ra]; i2[ra]=i1[ra]; v1[ra]=d1; i1[ra]=col+1; }
                else if (d1 < v2[ra]) { v2[ra]=d1; i2[ra]=col+1; }
                if (d2 < v1[rb]) { v2[rb]=v1[rb]; i2[rb]=i1[rb]; v1[rb]=d2; i1[rb]=col; }
                else if (d2 < v2[rb]) { v2[rb]=d2; i2[rb]=col; }
                if (d3 < v1[rb]) { v2[rb]=v1[rb]; i2[rb]=i1[rb]; v1[rb]=d3; i1[rb]=col+1; }
                else if (d3 < v2[rb]) { v2[rb]=d3; i2[rb]=col+1; }
                *(float2*)(dra + col) = make_float2(d0, d1);
                *(float2*)(drb + col) = make_float2(d2, d3);
            }
        }
    }

    // dump 32 candidate (v,i) slots per row
    #pragma unroll
    for (int ri = 0; ri < 4; ++ri) {
        const int row = wm * 32 + (ri >> 1) * 16 + (ri & 1) * 8 + lg;
        const int base = row * 32 + wn * 8 + q * 2;
        cand[base]     = make_float2(v1[ri], __int_as_float(i1[ri]));
        cand[base + 1] = make_float2(v2[ri], __int_as_float(i2[ri]));
    }
    __syncthreads();

    // refine: one warp per 8 rows; 32 slots = one per lane.
    // Exact s uses the SAME f2+e2-2dot formula as the stored distances so
    // fp32 rounding ties resolve identically (argmin tie -> lowest index).
    for (int j = 0; j < 8; ++j) {
        const int row = w * 8 + j;
        const float f2row = f2_s[row];
        float2 e = cand[row * 32 + lane];
        float cv = e.x;
        int   ci = __float_as_int(e.y);
        float vmin = cv;
        #pragma unroll
        for (int off = 16; off > 0; off >>= 1)
            vmin = fminf(vmin, __shfl_xor_sync(0xffffffffu, vmin, off));
        unsigned mask = __ballot_sync(0xffffffffu, cv <= vmin + MARGIN);
        int widx;
        if (__popc(mask) == 1) {
            widx = __shfl_sync(0xffffffffu, ci, __ffs(mask) - 1);
        } else {
            const int d0 = 2 * lane, d1 = 2 * lane + 1;
            const float z0 = zbase[(size_t)d0 * 1024 + row];
            const float z1 = zbase[(size_t)d1 * 1024 + row];
            float bs = 3.0e38f;
            int   bidx = 0x7fffffff;
            unsigned mm = mask;
            while (mm) {
                const int src = __ffs(mm) - 1;
                mm &= mm - 1;
                const int cidx = __shfl_sync(0xffffffffu, ci, src);
                const float* er = emb + (size_t)cidx * DDIM;
                float p = fmaf(z0, er[d0], z1 * er[d1]);
                #pragma unroll
                for (int off = 16; off > 0; off >>= 1)
                    p += __shfl_xor_sync(0xffffffffu, p, off);
                float s = fmaf(-2.0f, p, f2row + e2_s[cidx]);
                if (s < bs || (s == bs && cidx < bidx)) { bs = s; bidx = cidx; }
            }
            widx = bidx;
        }
        if (lane == 0) {
            idx_s[row] = widx;
            idx_out[n0 + row] = (float)widx;
            atomicAdd(&g_counts[widx], 1u);
        }
    }
    __syncthreads();

    // z_q gather/scatter + loss partial (coalesced over m)
    float lsum = 0.0f;
    {
        float* zq_base = zq_out + (size_t)b * (DDIM * 1024) + hw0;
        #pragma unroll 4
        for (int it = 0; it < 16; ++it) {
            int li = it * NTHREADS + t, d = li >> 7, m = li & 127;
            float v  = emb[(size_t)idx_s[m] * DDIM + d];
            float fv = zbase[(size_t)d * 1024 + m];
            float df = v - fv;
            lsum = fmaf(df, df, lsum);
            zq_base[(size_t)d * 1024 + m] = v;
        }
    }
    red[t] = lsum;
    __syncthreads();
    #pragma unroll
    for (int s = 256; s > 0; s >>= 1) {
        if (t < s) red[t] += red[t + s];
        __syncthreads();
    }
    if (t == 0) atomicAdd(&g_loss, red[0]);
}

__global__ void vq_finalize_kernel(float* __restrict__ loss_out,
                                   float* __restrict__ perp_out)
{
    __shared__ float red[KCB];
    int t = threadIdx.x;
    float c = (float)g_counts[t];
    float p = c * (1.0f / (float)NROWS);
    red[t] = p * logf(p + 1e-10f);
    __syncthreads();
    #pragma unroll
    for (int s = KCB / 2; s > 0; s >>= 1) {
        if (t < s) red[t] += red[t + s];
        __syncthreads();
    }
    if (t == 0) {
        *perp_out = expf(-red[0]);
        *loss_out = g_loss * (1.25f / (float)(NROWS * DDIM));
    }
}

extern "C" void kernel_launch(void* const* d_in, const int* in_sizes, int n_in,
                              void* d_out, int out_size)
{
    const float* z_e = (const float*)d_in[0];
    const float* emb = (const float*)d_in[1];
    float* out = (float*)d_out;

    cudaFuncSetAttribute(vq_main_kernel,
                         cudaFuncAttributeMaxDynamicSharedMemorySize, SMEM_BYTES);

    vq_prepack_kernel<<<65, 256>>>(emb);
    vq_main_kernel<<<NROWS / MT, NTHREADS, SMEM_BYTES>>>(
        z_e, emb, out + O_ZQ, out + O_IDX, out + O_DIST);
    vq_finalize_kernel<<<1, KCB>>>(out + O_LOSS, out + O_PERP);
}

// round 12
// speedup vs baseline: 1.2947x; 1.0365x over previous
#include <cuda_runtime.h>
#include <cuda_fp16.h>

#define NROWS 32768
#define DDIM  64
#define KCB   1024
#define MT    128
#define NTILES 8
#define NTHREADS 256

#define O_ZQ    0
#define O_LOSS  2097152
#define O_PERP  2097153
#define O_IDX   2097154
#define O_DIST  2129922

// g1-only K layout: 64 halves + pad -> pitch 72 (word stride 36 -> conflict-free)
#define KP 72
#define B_TILE 18432               // 128 codes x 144 B
#define B_ALL  147456              // full codebook

// smem byte offsets
#define S_A    0                   // 128 x 144 = 18432
#define S_B    18432               // 147456 (whole codebook, resident)
#define S_E2   165888              // 1024 f32
#define S_F2   169984              // 128 f32
#define S_CAND 170496              // 128 rows x 32 key slots x 4B = 16384
#define S_IDX  186880              // 128 i32
#define S_RED  187392              // 256 f32
#define SMEM_BYTES 188416

#define ESCALE 1024.0f
#define DSCALE (-2.0f / 1024.0f)   // exact power of two
#define MARGIN 6e-4f
#define KBASE  0x41000000u         // 8.0f; dist in (8,1024) w.p. ~1 (dist>=~25)

__device__ float         g_loss;
__device__ unsigned int  g_counts[KCB];
__device__ float         g_e2[KCB];
__device__ __align__(16) unsigned char g_epack[B_ALL];

__device__ __forceinline__ unsigned smem_u32(const void* p) {
    unsigned a;
    asm("{ .reg .u64 t; cvta.to.shared.u64 t, %1; cvt.u32.u64 %0, t; }"
        : "=r"(a) : "l"(p));
    return a;
}
__device__ __forceinline__ void cp16(unsigned dst, const void* src) {
    asm volatile("cp.async.cg.shared.global [%0], [%1], 16;" :: "r"(dst), "l"(src));
}
#define CP_COMMIT() asm volatile("cp.async.commit_group;" ::: "memory")
#define CP_WAIT0()  asm volatile("cp.async.wait_group 0;"  ::: "memory")

__device__ __forceinline__ void mma16816(float* c, const unsigned* a,
                                         unsigned b0, unsigned b1) {
    asm volatile(
        "mma.sync.aligned.m16n8k16.row.col.f32.f16.f16.f32 "
        "{%0,%1,%2,%3}, {%4,%5,%6,%7}, {%8,%9}, {%0,%1,%2,%3};"
        : "+f"(c[0]), "+f"(c[1]), "+f"(c[2]), "+f"(c[3])
        : "r"(a[0]), "r"(a[1]), "r"(a[2]), "r"(a[3]), "r"(b0), "r"(b1));
}

// branchless top-2 on integer keys: 3x IMNMX, no predicates
__device__ __forceinline__ void top2(unsigned& k1, unsigned& k2, unsigned key) {
    unsigned hi = max(k1, key);
    k1 = min(k1, key);
    k2 = min(k2, hi);
}

// ---- prepack: g1 = fp16(1024*emb) rows (pitch KP) + e2; block 64 zeroes scratch ----
__global__ void vq_prepack_kernel(const float* __restrict__ emb) {
    const int t = threadIdx.x;
    if (blockIdx.x == 64) {
        for (int i = t; i < KCB; i += NTHREADS) g_counts[i] = 0u;
        if (t == 0) g_loss = 0.0f;
        return;
    }
    const int kk = t >> 4, part = t & 15;
    const int k = blockIdx.x * 16 + kk;
    const float* ep = emb + (size_t)k * DDIM + part * 4;
    __half* row = (__half*)(g_epack + (size_t)k * (KP * 2));
    float e2p = 0.0f;
    #pragma unroll
    for (int i = 0; i < 4; i += 2) {
        float x0 = ep[i], x1 = ep[i + 1];
        e2p = fmaf(x0, x0, e2p);
        e2p = fmaf(x1, x1, e2p);
        __half a0 = __float2half_rn(x0 * ESCALE);
        __half a1 = __float2half_rn(x1 * ESCALE);
        *(__half2*)(row + part * 4 + i) = __halves2half2(a0, a1);
    }
    #pragma unroll
    for (int off = 8; off > 0; off >>= 1)
        e2p += __shfl_xor_sync(0xffffffffu, e2p, off, 16);
    if (part == 0) g_e2[k] = e2p;
}

__global__ void __launch_bounds__(NTHREADS, 1)
vq_main_kernel(const float* __restrict__ z_e,
               const float* __restrict__ emb,
               float* __restrict__ zq_out,
               float* __restrict__ idx_out,
               float* __restrict__ dist_out)
{
    extern __shared__ unsigned char smem[];
    const unsigned sbase = smem_u32(smem);
    const int t = threadIdx.x, lane = t & 31, w = t >> 5;
    const int wm = w & 3, wn = w >> 2;          // 4 row-quads x 2 col-halves
    const int q = lane & 3, lg = lane >> 2;

    const int n0 = blockIdx.x * MT, b = n0 >> 10, hw0 = n0 & 1023;
    const float* zbase = z_e + (size_t)b * (DDIM * 1024) + hw0;

    __half*   A_s  = (__half*)(smem + S_A);
    float*    e2_s = (float*)(smem + S_E2);
    float*    f2_s = (float*)(smem + S_F2);
    unsigned* candU = (unsigned*)(smem + S_CAND);
    int*      idx_s = (int*)(smem + S_IDX);
    float*    red  = (float*)(smem + S_RED);

    // load whole codebook-g1 into smem (36 x 16B per thread)
    #pragma unroll
    for (int i = 0; i < 36; ++i) {
        int c = i * NTHREADS + t;
        cp16(sbase + S_B + c * 16, g_epack + c * 16);
    }
    CP_COMMIT();

    // build A = h1 fp16 (pitch KP) + f2, strided direct loads
    {
        const int m = t >> 1, hf = t & 1;
        __half* arow = A_s + m * KP;
        float f2p = 0.0f;
        #pragma unroll
        for (int i = 0; i < 32; i += 2) {
            int d = hf * 32 + i;
            float x0 = zbase[(size_t)d * 1024 + m];
            float x1 = zbase[(size_t)(d + 1) * 1024 + m];
            f2p = fmaf(x0, x0, f2p);
            f2p = fmaf(x1, x1, f2p);
            *(__half2*)(arow + d) =
                __halves2half2(__float2half_rn(x0), __float2half_rn(x1));
        }
        float oth = __shfl_xor_sync(0xffffffffu, f2p, 1);
        if (hf == 0) f2_s[m] = f2p + oth;
    }
    #pragma unroll
    for (int i = 0; i < 4; ++i) e2_s[i * NTHREADS + t] = g_e2[i * NTHREADS + t];
    CP_WAIT0();
    __syncthreads();

    // 8 independent key chains: c = ri*2 + parity, ri = mt*2 + (0: row r, 1: row r+8)
    unsigned k1[8], k2[8];
    #pragma unroll
    for (int i = 0; i < 8; ++i) { k1[i] = 0xFFFFFFFFu; k2[i] = 0xFFFFFFFFu; }

    const float f2a0 = f2_s[wm * 32 + lg];
    const float f2b0 = f2_s[wm * 32 + lg + 8];
    const float f2a1 = f2_s[wm * 32 + 16 + lg];
    const float f2b1 = f2_s[wm * 32 + 16 + lg + 8];

    #pragma unroll 1
    for (int t8 = 0; t8 < NTILES; ++t8) {
        const __half* B_s = (const __half*)(smem + S_B + t8 * B_TILE);

        float C[2][8][4];
        #pragma unroll
        for (int mt = 0; mt < 2; ++mt)
            #pragma unroll
            for (int nt = 0; nt < 8; ++nt)
                #pragma unroll
                for (int r = 0; r < 4; ++r) C[mt][nt][r] = 0.0f;

        #pragma unroll
        for (int kt = 0; kt < 4; ++kt) {
            const int k0 = kt * 16 + 2 * q;
            unsigned a[2][4];
            #pragma unroll
            for (int mt = 0; mt < 2; ++mt) {
                const int r = wm * 32 + mt * 16 + lg;
                a[mt][0] = *(const unsigned*)(A_s + r * KP + k0);
                a[mt][1] = *(const unsigned*)(A_s + (r + 8) * KP + k0);
                a[mt][2] = *(const unsigned*)(A_s + r * KP + k0 + 8);
                a[mt][3] = *(const unsigned*)(A_s + (r + 8) * KP + k0 + 8);
            }
            #pragma unroll
            for (int nt = 0; nt < 8; ++nt) {
                const int n = wn * 64 + nt * 8 + lg;
                unsigned b0 = *(const unsigned*)(B_s + n * KP + k0);
                unsigned b1 = *(const unsigned*)(B_s + n * KP + k0 + 8);
                mma16816(C[0][nt], a[0], b0, b1);
                mma16816(C[1][nt], a[1], b0, b1);
            }
        }

        // epilogue: approx distances, integer-key top-2 (no predicates), float2 stores
        #pragma unroll
        for (int mt = 0; mt < 2; ++mt) {
            const int r = wm * 32 + mt * 16 + lg;
            const float f2a = mt ? f2a1 : f2a0;
            const float f2b = mt ? f2b1 : f2b0;
            float* dra = dist_out + (size_t)(n0 + r) * KCB;
            float* drb = dist_out + (size_t)(n0 + r + 8) * KCB;
            #pragma unroll
            for (int nt = 0; nt < 8; ++nt) {
                const int col = t8 * 128 + wn * 64 + nt * 8 + 2 * q;
                const unsigned tc = (unsigned)(t8 * 8 + nt);    // column-monotonic
                const float e2x = e2_s[col], e2y = e2_s[col + 1];
                float d0 = fmaf(DSCALE, C[mt][nt][0], f2a + e2x);
                float d1 = fmaf(DSCALE, C[mt][nt][1], f2a + e2y);
                float d2 = fmaf(DSCALE, C[mt][nt][2], f2b + e2x);
                float d3 = fmaf(DSCALE, C[mt][nt][3], f2b + e2y);
                top2(k1[mt*4+0], k2[mt*4+0], (__float_as_uint(d0) - KBASE) * 64u + tc);
                top2(k1[mt*4+1], k2[mt*4+1], (__float_as_uint(d1) - KBASE) * 64u + tc);
                top2(k1[mt*4+2], k2[mt*4+2], (__float_as_uint(d2) - KBASE) * 64u + tc);
                top2(k1[mt*4+3], k2[mt*4+3], (__float_as_uint(d3) - KBASE) * 64u + tc);
                *(float2*)(dra + col) = make_float2(d0, d1);
                *(float2*)(drb + col) = make_float2(d2, d3);
            }
        }
    }

    // dump 32 key slots per row: slot = wn*16 + q*4 + p*2 + rank
    #pragma unroll
    for (int ri = 0; ri < 4; ++ri) {
        const int row = wm * 32 + (ri >> 1) * 16 + (ri & 1) * 8 + lg;
        const int c = (ri >> 1) * 4 + (ri & 1) * 2;   // chain base: mt*4 + (b?2:0)
        unsigned* cb = candU + row * 32 + wn * 16 + q * 4;
        cb[0] = k1[c];
        cb[1] = k2[c];
        cb[2] = k1[c + 1];
        cb[3] = k2[c + 1];
    }
    __syncthreads();

    // refine: one warp per 16 rows; 32 slots = one key per lane.
    // Exact s uses the SAME f2+e2-2dot formula as the stored distances so
    // fp32 rounding ties resolve identically (argmin tie -> lowest index).
    for (int j = 0; j < 16; ++j) {
        const int row = w * 16 + j;
        const float f2row = f2_s[row];
        const unsigned key = candU[row * 32 + lane];
        const float cv = __uint_as_float((key >> 6) + KBASE);
        const int tcode = (int)(key & 63u);
        const int ci = (tcode >> 3) * 128 + (lane >> 4) * 64 + (tcode & 7) * 8
                     + ((lane >> 2) & 3) * 2 + ((lane >> 1) & 1);
        float vmin = cv;
        #pragma unroll
        for (int off = 16; off > 0; off >>= 1)
            vmin = fminf(vmin, __shfl_xor_sync(0xffffffffu, vmin, off));
        unsigned mask = __ballot_sync(0xffffffffu, cv <= vmin + MARGIN);
        int widx;
        if (__popc(mask) == 1) {
            widx = __shfl_sync(0xffffffffu, ci, __ffs(mask) - 1);
        } else {
            const int d0 = 2 * lane, d1 = 2 * lane + 1;
            const float z0 = zbase[(size_t)d0 * 1024 + row];
            const float z1 = zbase[(size_t)d1 * 1024 + row];
            float bs = 3.0e38f;
            int   bidx = 0x7fffffff;
            unsigned mm = mask;
            while (mm) {
                const int src = __ffs(mm) - 1;
                mm &= mm - 1;
                const int cidx = __shfl_sync(0xffffffffu, ci, src);
                const float* er = emb + (size_t)cidx * DDIM;
                float p = fmaf(z0, er[d0], z1 * er[d1]);
                #pragma unroll
                for (int off = 16; off > 0; off >>= 1)
                    p += __shfl_xor_sync(0xffffffffu, p, off);
                float s = fmaf(-2.0f, p, f2row + e2_s[cidx]);
                if (s < bs || (s == bs && cidx < bidx)) { bs = s; bidx = cidx; }
            }
            widx = bidx;
        }
        if (lane == 0) {
            idx_s[row] = widx;
            idx_out[n0 + row] = (float)widx;
            atomicAdd(&g_counts[widx], 1u);
        }
    }
    __syncthreads();

    // z_q gather/scatter + loss partial
    float lsum = 0.0f;
    {
        const int m = t >> 1, hf = t & 1;
        const int bi = idx_s[m];
        const float* erow = emb + (size_t)bi * DDIM;
        float* zq_base = zq_out + (size_t)b * (DDIM * 1024) + hw0;
        #pragma unroll
        for (int i = 0; i < 32; ++i) {
            int d = hf * 32 + i;
            float v  = erow[d];
            float fv = zbase[(size_t)d * 1024 + m];
            float df = v - fv;
            lsum = fmaf(df, df, lsum);
            zq_base[(size_t)d * 1024 + m] = v;
        }
    }
    red[t] = lsum;
    __syncthreads();
    #pragma unroll
    for (int s = 128; s > 0; s >>= 1) {
        if (t < s) red[t] += red[t + s];
        __syncthreads();
    }
    if (t == 0) atomicAdd(&g_loss, red[0]);
}

__global__ void vq_finalize_kernel(float* __restrict__ loss_out,
                                   float* __restrict__ perp_out)
{
    __shared__ float red[KCB];
    int t = threadIdx.x;
    float c = (float)g_counts[t];
    float p = c * (1.0f / (float)NROWS);
    red[t] = p * logf(p + 1e-10f);
    __syncthreads();
    #pragma unroll
    for (int s = KCB / 2; s > 0; s >>= 1) {
        if (t < s) red[t] += red[t + s];
        __syncthreads();
    }
    if (t == 0) {
        *perp_out = expf(-red[0]);
        *loss_out = g_loss * (1.25f / (float)(NROWS * DDIM));
    }
}

extern "C" void kernel_launch(void* const* d_in, const int* in_sizes, int n_in,
                              void* d_out, int out_size)
{
    const float* z_e = (const float*)d_in[0];
    const float* emb = (const float*)d_in[1];
    float* out = (float*)d_out;

    cudaFuncSetAttribute(vq_main_kernel,
                         cudaFuncAttributeMaxDynamicSharedMemorySize, SMEM_BYTES);

    vq_prepack_kernel<<<65, NTHREADS>>>(emb);
    vq_main_kernel<<<NROWS / MT, NTHREADS, SMEM_BYTES>>>(
        z_e, emb, out + O_ZQ, out + O_IDX, out + O_DIST);
    vq_finalize_kernel<<<1, KCB>>>(out + O_LOSS, out + O_PERP);
}